// round 16
// baseline (speedup 1.0000x reference)
#include <cuda_runtime.h>
#include <cuda_bf16.h>
#include <math.h>
#include <stdint.h>

#define D_IN 768
#define H    256
#define NB   64
#define NT   512
#define BT   (NB*NT)    // 32768
#define G3   768        // 3*H
#define SNC  64         // scan CTAs (each owns 4 h-columns)
#define SNT  256        // scan threads

// ---------------- scratch ----------------
__device__ float g_gi1[BT * (size_t)G3];                 // 96 MB time-major (t*64+b)
__device__ float g_gi2[BT * (size_t)G3];                 // 96 MB
__device__ __nv_bfloat16 g_Abuf[BT * (size_t)(3*D_IN)];  // [x_hi|x_lo|x_hi] time-major
__device__ __nv_bfloat16 g_A3[BT * (size_t)(3*H)];       // [h_hi|h_lo|h_hi] time-major
__device__ __nv_bfloat16 g_B1[(size_t)G3 * (3*D_IN)];
__device__ __nv_bfloat16 g_B2[(size_t)G3 * (3*D_IN)];
__device__ __nv_bfloat16 g_B3[(size_t)G3 * (3*H)];
__device__ __nv_bfloat16 g_hsplit[2][NB * 512];          // h state [b][hi(256)|lo(256)]
__device__ __nv_bfloat16 g_Wr1[SNC * 16 * 512];          // per-CTA scan weights [Whi|Wlo]
__device__ __nv_bfloat16 g_Wr2[SNC * 16 * 512];
__device__ unsigned g_cnt;                               // monotonic barrier counter

// ---------------- helpers ----------------
__device__ __forceinline__ uint32_t smem_u32(const void* p) {
    uint32_t a;
    asm("{ .reg .u64 t; cvta.to.shared.u64 t, %1; cvt.u32.u64 %0, t; }" : "=r"(a) : "l"(p));
    return a;
}
__device__ __forceinline__ void ldsm_x4(uint32_t& r0, uint32_t& r1, uint32_t& r2, uint32_t& r3,
                                        uint32_t addr) {
    asm volatile("ldmatrix.sync.aligned.m8n8.x4.shared.b16 {%0,%1,%2,%3}, [%4];"
                 : "=r"(r0), "=r"(r1), "=r"(r2), "=r"(r3) : "r"(addr));
}
__device__ __forceinline__ void mma_bf16(float* c, const uint32_t* a, const uint32_t* b) {
    asm volatile("mma.sync.aligned.m16n8k16.row.col.f32.bf16.bf16.f32 "
                 "{%0,%1,%2,%3}, {%4,%5,%6,%7}, {%8,%9}, {%0,%1,%2,%3};"
                 : "+f"(c[0]), "+f"(c[1]), "+f"(c[2]), "+f"(c[3])
                 : "r"(a[0]), "r"(a[1]), "r"(a[2]), "r"(a[3]), "r"(b[0]), "r"(b[1]));
}
__device__ __forceinline__ void cp16(uint32_t dst, const void* src) {
    asm volatile("cp.async.cg.shared.global [%0], [%1], 16;" :: "r"(dst), "l"(src));
}
__device__ __forceinline__ void cp_commit() { asm volatile("cp.async.commit_group;"); }
__device__ __forceinline__ void cp_wait1()  { asm volatile("cp.async.wait_group 1;"); }
__device__ __forceinline__ void cp_wait0()  { asm volatile("cp.async.wait_group 0;"); }

// gemm smem tile swizzle (64B rows, proven)
__device__ __forceinline__ uint32_t sw_off(int row, int c) {
    return ((uint32_t)row << 6) + (((uint32_t)(c ^ ((row >> 1) & 3))) << 4);
}
// scan smem tile swizzle (1024B rows, 16B chunks)
__device__ __forceinline__ uint32_t sw1k(int row, int c) {
    return ((uint32_t)row << 10) + (((uint32_t)(c ^ (row & 7))) << 4);
}
__device__ __forceinline__ float sigmoidf_(float x) {
    return 1.0f / (1.0f + __expf(-x));
}
__device__ __forceinline__ float tanhf_(float x) {
    float e = __expf(-2.0f * x);
    return (1.0f - e) / (1.0f + e);
}

// ---------------- prep kernels ----------------
__global__ void prepA_kernel(const float* __restrict__ x, __nv_bfloat16* __restrict__ A) {
    long i = (long)blockIdx.x * blockDim.x + threadIdx.x;
    if (i >= (long)BT * D_IN) return;
    int k = (int)(i % D_IN);
    long row = i / D_IN;              // b*512 + t
    int b = (int)(row >> 9), t = (int)(row & 511);
    float v = x[i];
    __nv_bfloat16 hi = __float2bfloat16(v);
    __nv_bfloat16 lo = __float2bfloat16(v - __bfloat162float(hi));
    long orow = ((long)t * 64 + b) * (3 * D_IN);
    A[orow + k] = hi;
    A[orow + D_IN + k] = lo;
    A[orow + 2 * D_IN + k] = hi;
}

__device__ __forceinline__ void prep_one(const float* __restrict__ W, int Kin,
                                         __nv_bfloat16* __restrict__ Bm, long idx) {
    int n = (int)(idx / Kin), k = (int)(idx % Kin);
    float v = W[(size_t)k * G3 + n];
    __nv_bfloat16 hi = __float2bfloat16(v);
    __nv_bfloat16 lo = __float2bfloat16(v - __bfloat162float(hi));
    size_t o = (size_t)n * (3 * Kin);
    Bm[o + k] = hi;
    Bm[o + Kin + k] = hi;
    Bm[o + 2 * Kin + k] = lo;
}

__global__ void prepB_all(const float* __restrict__ W1, const float* __restrict__ W2,
                          const float* __restrict__ W3,
                          __nv_bfloat16* __restrict__ B1, __nv_bfloat16* __restrict__ B2,
                          __nv_bfloat16* __restrict__ B3) {
    long i = (long)blockIdx.x * blockDim.x + threadIdx.x;
    const long n1 = (long)G3 * D_IN;
    const long n3 = (long)G3 * H;
    if (i < n1)               prep_one(W1, D_IN, B1, i);
    else if (i < 2 * n1)      prep_one(W2, D_IN, B2, i - n1);
    else if (i < 2 * n1 + n3) prep_one(W3, H,    B3, i - 2 * n1);
}

// per-CTA scan weights (16-row tiles, rows 12-15 zero) + zero h + reset barrier
__global__ void prepWhh(const float* __restrict__ Whh, __nv_bfloat16* __restrict__ dst) {
    long i = (long)blockIdx.x * blockDim.x + threadIdx.x;
    if (i < 2L * NB * 512) ((__nv_bfloat16*)g_hsplit)[i] = __float2bfloat16(0.0f);
    if (i == 0) g_cnt = 0u;
    if (i >= (long)SNC * 16 * 512) return;
    int cb = (int)(i / (16 * 512));
    int rem = (int)(i % (16 * 512));
    int nn = rem / 512, k2 = rem % 512;
    if (nn >= 12) { dst[i] = __float2bfloat16(0.0f); return; }
    int g = nn >> 2, j = nn & 3;
    int wcol = g * 256 + cb * 4 + j;
    float v = Whh[(size_t)(k2 & 255) * G3 + wcol];
    __nv_bfloat16 hi = __float2bfloat16(v);
    dst[i] = (k2 < 256) ? hi : __float2bfloat16(v - __bfloat162float(hi));
}

// ---------------- HMMA GEMM (unchanged, proven) ----------------
__global__ void __launch_bounds__(256)
gemm_mma(const __nv_bfloat16* __restrict__ A, const __nv_bfloat16* __restrict__ Bm,
         int K, const float* __restrict__ bias, float* __restrict__ C, int acc)
{
    __shared__ __align__(1024) char smA[2][8192];
    __shared__ __align__(1024) char smB[2][8192];

    const int tid = threadIdx.x;
    const int wid = tid >> 5, lid = tid & 31;
    const int warp_m = wid & 3, warp_n = wid >> 2;
    const int m0 = blockIdx.y * 128, n0 = blockIdx.x * 128;

    const __nv_bfloat16* Ag = A + (size_t)m0 * K;
    const __nv_bfloat16* Bg = Bm + (size_t)n0 * K;

    const uint32_t sA[2] = { smem_u32(smA[0]), smem_u32(smA[1]) };
    const uint32_t sB[2] = { smem_u32(smB[0]), smem_u32(smB[1]) };

    const int lrow0 = tid >> 2;
    const int lc    = tid & 3;
    const uint32_t loff0 = sw_off(lrow0, lc);
    const uint32_t loff1 = sw_off(lrow0 + 64, lc);

    float accf[2][8][4];
#pragma unroll
    for (int i = 0; i < 2; i++)
#pragma unroll
        for (int j = 0; j < 8; j++)
#pragma unroll
            for (int q = 0; q < 4; q++) accf[i][j][q] = 0.0f;

    const int nk = K >> 5;

    {
        const char* ga0 = (const char*)(Ag + (size_t)lrow0 * K + lc * 8);
        const char* ga1 = (const char*)(Ag + (size_t)(lrow0 + 64) * K + lc * 8);
        const char* gb0 = (const char*)(Bg + (size_t)lrow0 * K + lc * 8);
        const char* gb1 = (const char*)(Bg + (size_t)(lrow0 + 64) * K + lc * 8);
        cp16(sA[0] + loff0, ga0); cp16(sA[0] + loff1, ga1);
        cp16(sB[0] + loff0, gb0); cp16(sB[0] + loff1, gb1);
        cp_commit();
    }

    const int a_row = (lid & 15);
    const int a_cd  = (lid >> 4);
    const int b_row = (lid & 7) + ((lid >> 4) & 1) * 8;
    const int b_cd  = (lid >> 3) & 1;

    for (int kc = 0; kc < nk; kc++) {
        if (kc + 1 < nk) {
            int koff = (kc + 1) * 32;
            int st = (kc + 1) & 1;
            const char* ga0 = (const char*)(Ag + (size_t)lrow0 * K + koff + lc * 8);
            const char* ga1 = (const char*)(Ag + (size_t)(lrow0 + 64) * K + koff + lc * 8);
            const char* gb0 = (const char*)(Bg + (size_t)lrow0 * K + koff + lc * 8);
            const char* gb1 = (const char*)(Bg + (size_t)(lrow0 + 64) * K + koff + lc * 8);
            cp16(sA[st] + loff0, ga0); cp16(sA[st] + loff1, ga1);
            cp16(sB[st] + loff0, gb0); cp16(sB[st] + loff1, gb1);
        }
        cp_commit();
        cp_wait1();
        __syncthreads();

        const uint32_t aT = sA[kc & 1], bT = sB[kc & 1];
#pragma unroll
        for (int ks = 0; ks < 2; ks++) {
            uint32_t afr[2][4];
#pragma unroll
            for (int fm = 0; fm < 2; fm++) {
                int row = warp_m * 32 + fm * 16 + a_row;
                ldsm_x4(afr[fm][0], afr[fm][1], afr[fm][2], afr[fm][3],
                        aT + sw_off(row, 2 * ks + a_cd));
            }
            uint32_t bfr[8][2];
#pragma unroll
            for (int ng = 0; ng < 4; ng++) {
                int row = warp_n * 64 + ng * 16 + b_row;
                uint32_t r0, r1, r2, r3;
                ldsm_x4(r0, r1, r2, r3, bT + sw_off(row, 2 * ks + b_cd));
                bfr[ng * 2][0] = r0;     bfr[ng * 2][1] = r1;
                bfr[ng * 2 + 1][0] = r2; bfr[ng * 2 + 1][1] = r3;
            }
#pragma unroll
            for (int fm = 0; fm < 2; fm++)
#pragma unroll
                for (int fn = 0; fn < 8; fn++)
                    mma_bf16(accf[fm][fn], afr[fm], bfr[fn]);
        }
        __syncthreads();
    }

#pragma unroll
    for (int fm = 0; fm < 2; fm++) {
        int row = m0 + warp_m * 32 + fm * 16 + (lid >> 2);
#pragma unroll
        for (int fn = 0; fn < 8; fn++) {
            int colg = n0 + warp_n * 64 + fn * 8 + (lid & 3) * 2;
            float2 v0 = make_float2(accf[fm][fn][0], accf[fm][fn][1]);
            float2 v1 = make_float2(accf[fm][fn][2], accf[fm][fn][3]);
            if (bias) {
                float b0 = bias[colg], b1 = bias[colg + 1];
                v0.x += b0; v0.y += b1; v1.x += b0; v1.y += b1;
            }
            float* p0 = C + (size_t)row * G3 + colg;
            float* p1 = C + (size_t)(row + 8) * G3 + colg;
            if (acc) {
                float2 o0 = *(const float2*)p0;
                float2 o1 = *(const float2*)p1;
                v0.x += o0.x; v0.y += o0.y; v1.x += o1.x; v1.y += o1.y;
            }
            *(float2*)p0 = v0;
            *(float2*)p1 = v1;
        }
    }
}

// ---------------- tensor-core persistent scan (v4: split-k fill/MMA overlap) ----------------
// 64 CTAs x 256 thr. CTA cb owns h-cols c0..c0+3 -> 12 weight cols (pad 16).
// Per warp, A-fill split into two cp.async groups by k-half so the second
// half's L2 latency hides under the first half's MMA.
#define AS_OFF   0
#define BS_OFF   65536
#define PART_OFF 81920
#define PSTR     20
#define SCAN_SMEM (PART_OFF + 2*64*PSTR*4)

__global__ void __launch_bounds__(SNT, 1)
scan_tc(const float* __restrict__ gi, const __nv_bfloat16* __restrict__ Wsc,
        const float* __restrict__ bhh, const float* __restrict__ tau,
        float* __restrict__ out, int outc0, __nv_bfloat16* __restrict__ a3)
{
    extern __shared__ char sm[];
    const uint32_t as_u = smem_u32(sm + AS_OFF);
    const uint32_t bs_u = smem_u32(sm + BS_OFF);
    float* part = (float*)(sm + PART_OFF);

    const int cb  = blockIdx.x;
    const int tid = threadIdx.x;
    const int wid = tid >> 5, lid = tid & 31;
    const int c0  = cb * 4;
    const int wm  = wid & 3;          // M-tile (16 rows)
    const int khh = wid >> 2;         // k-half

    const int eb  = tid >> 2;         // epilogue batch row (0..63)
    const int ejj = tid & 3;          // epilogue col (0..3)
    const int col = c0 + ejj;

    float bias[3];
#pragma unroll
    for (int g = 0; g < 3; g++) bias[g] = bhh[g * 256 + col];
    const float invt = 1.0f / tau[0];
    float hold1 = 0.0f;               // exact fp32 recurrent carry

    // stationary weights -> smem (one-time): 16 rows x 64 chunks
    for (int i = tid; i < 1024; i += SNT) {
        int n = i >> 6, c = i & 63;
        cp16(bs_u + sw1k(n, c), Wsc + (size_t)cb * 16 * 512 + n * 512 + c * 8);
    }
    cp_commit();
    cp_wait0();
    __syncthreads();

    // resident B fragments: per kt one x4 (16 B-rows = 2 n8-tiles), hi + lo
    const int b_row = (lid & 7) + ((lid >> 4) & 1) * 8;
    const int b_cd  = (lid >> 3) & 1;
    uint32_t bH[8][4], bL[8][4];
#pragma unroll
    for (int ii = 0; ii < 8; ii++) {
        int kt = khh * 8 + ii;
        ldsm_x4(bH[ii][0], bH[ii][1], bH[ii][2], bH[ii][3],
                bs_u + sw1k(b_row, 2 * kt + b_cd));
        ldsm_x4(bL[ii][0], bL[ii][1], bL[ii][2], bL[ii][3],
                bs_u + sw1k(b_row, 2 * (16 + kt) + b_cd));
    }

    // gi register prefetch for t=0 (one col per thread)
    const float* g0 = gi + (size_t)eb * G3 + col;
    float pr = g0[0], pz = g0[256], pn = g0[512];

    const int a_row = wm * 16 + (lid & 15);
    const int a_cd  = lid >> 4;
    const int fl_c  = (lid < 16) ? (khh * 16 + lid) : (32 + khh * 16 + (lid - 16));
    // lanes 0-7 & 16-23 own the chunks used by this warp's first 4 kt
    const bool own0 = ((lid >> 3) & 1) == 0;

    for (int t = 0; t < NT; t++) {
        const int cur = t & 1, nxt = cur ^ 1;
        const __nv_bfloat16* hsrc = g_hsplit[cur];

        // prefetch gi for t+1 (independent; hides behind MMA)
        int tnn = (t + 1 < NT) ? t + 1 : t;
        const float* gx = gi + ((size_t)tnn * 64 + eb) * G3 + col;
        float tr = gx[0], tz = gx[256], tn2 = gx[512];

        // A fill, two groups by k-half (each lane owns one chunk-col x 16 rows)
        if (own0) {
#pragma unroll
            for (int i = 0; i < 16; i++) {
                int row = wm * 16 + i;
                cp16(as_u + sw1k(row, fl_c), hsrc + row * 512 + fl_c * 8);
            }
        }
        cp_commit();            // group0: chunks for kt 0..3 of this warp
        if (!own0) {
#pragma unroll
            for (int i = 0; i < 16; i++) {
                int row = wm * 16 + i;
                cp16(as_u + sw1k(row, fl_c), hsrc + row * 512 + fl_c * 8);
            }
        }
        cp_commit();            // group1: chunks for kt 4..7

        float cf[2][4];
#pragma unroll
        for (int nt = 0; nt < 2; nt++)
#pragma unroll
            for (int q = 0; q < 4; q++) cf[nt][q] = 0.0f;

#pragma unroll
        for (int half = 0; half < 2; half++) {
            if (half == 0) cp_wait1(); else cp_wait0();
            __syncwarp();
#pragma unroll
            for (int jj2 = 0; jj2 < 4; jj2++) {
                int ii = half * 4 + jj2;
                int kt = khh * 8 + ii;
                uint32_t aH[4], aL[4];
                ldsm_x4(aH[0], aH[1], aH[2], aH[3], as_u + sw1k(a_row, 2 * kt + a_cd));
                ldsm_x4(aL[0], aL[1], aL[2], aL[3], as_u + sw1k(a_row, 2 * (16 + kt) + a_cd));
                mma_bf16(cf[0], aH, &bH[ii][0]);
                mma_bf16(cf[1], aH, &bH[ii][2]);
                mma_bf16(cf[0], aL, &bH[ii][0]);
                mma_bf16(cf[1], aL, &bH[ii][2]);
                mma_bf16(cf[0], aH, &bL[ii][0]);
                mma_bf16(cf[1], aH, &bL[ii][2]);
            }
        }

        // exchange partials: part[(khh*64 + row)*PSTR + n]
#pragma unroll
        for (int nt = 0; nt < 2; nt++) {
            int r0 = wm * 16 + (lid >> 2);
            int cc = nt * 8 + (lid & 3) * 2;
            *(float2*)&part[(khh * 64 + r0) * PSTR + cc]     = make_float2(cf[nt][0], cf[nt][1]);
            *(float2*)&part[(khh * 64 + r0 + 8) * PSTR + cc] = make_float2(cf[nt][2], cf[nt][3]);
        }
        __syncthreads();

        // gates (one col per thread; register carry + register gi)
        {
            const float* p0 = part + eb * PSTR;
            const float* p1 = part + (64 + eb) * PSTR;
            float sr = p0[ejj]     + p1[ejj];
            float sz = p0[4 + ejj] + p1[4 + ejj];
            float sn = p0[8 + ejj] + p1[8 + ejj];
            float r = sigmoidf_(pr + sr + bias[0]);
            float z = sigmoidf_(pz + sz + bias[1]);
            float n = tanhf_(pn + r * (sn + bias[2]));
            float hc = (1.0f - z) * n + z * hold1;
            float hnew = hold1 + invt * (hc - hold1);
            hold1 = hnew;

            __nv_bfloat16 nh = __float2bfloat16(hnew);
            __nv_bfloat16 nl = __float2bfloat16(hnew - __bfloat162float(nh));
            __nv_bfloat16* hd = g_hsplit[nxt] + eb * 512 + col;
            hd[0]   = nh;
            hd[256] = nl;
            out[((size_t)eb * NT + t) * 512 + outc0 + col] = hnew;
            if (a3) {
                __nv_bfloat16* ad = a3 + ((size_t)t * 64 + eb) * (3 * H) + col;
                ad[0]   = nh;
                ad[256] = nl;
                ad[512] = nh;
            }
        }
        __syncthreads();   // h stores sequenced before tid0's release-arrival

        if (tid == 0) {
            asm volatile("red.release.gpu.global.add.u32 [%0], %1;"
                         :: "l"(&g_cnt), "r"(1u) : "memory");
            unsigned tgt = (unsigned)SNC * (unsigned)(t + 1);
            unsigned v;
            do {
                asm volatile("ld.acquire.gpu.global.u32 %0, [%1];"
                             : "=r"(v) : "l"(&g_cnt) : "memory");
            } while (v < tgt);
        }
        __syncthreads();

        pr = tr; pz = tz; pn = tn2;
    }
}

// ---------------- launch (single stream; capture-safe) ----------------
extern "C" void kernel_launch(void* const* d_in, const int* in_sizes, int n_in,
                              void* d_out, int out_size) {
    const float* x    = (const float*)d_in[0];
    const float* tau1 = (const float*)d_in[1];
    const float* tau2 = (const float*)d_in[2];
    const float* Wih1 = (const float*)d_in[3];
    const float* Whh1 = (const float*)d_in[4];
    const float* bih1 = (const float*)d_in[5];
    const float* bhh1 = (const float*)d_in[6];
    const float* Wih2 = (const float*)d_in[7];
    const float* Whh2 = (const float*)d_in[8];
    const float* bih2 = (const float*)d_in[9];
    const float* bhh2 = (const float*)d_in[10];
    float* out = (float*)d_out;

    float *gi1, *gi2;
    __nv_bfloat16 *Ab, *A3, *B1, *B2, *B3, *Wr1, *Wr2;
    cudaGetSymbolAddress((void**)&gi1, g_gi1);
    cudaGetSymbolAddress((void**)&gi2, g_gi2);
    cudaGetSymbolAddress((void**)&Ab,  g_Abuf);
    cudaGetSymbolAddress((void**)&A3,  g_A3);
    cudaGetSymbolAddress((void**)&B1,  g_B1);
    cudaGetSymbolAddress((void**)&B2,  g_B2);
    cudaGetSymbolAddress((void**)&B3,  g_B3);
    cudaGetSymbolAddress((void**)&Wr1, g_Wr1);
    cudaGetSymbolAddress((void**)&Wr2, g_Wr2);

    cudaFuncSetAttribute(scan_tc,
                         cudaFuncAttributeMaxDynamicSharedMemorySize, SCAN_SMEM);

    dim3 ggrid(G3 / 128, BT / 128);   // (6, 256)
    int wgrid = (SNC * 16 * 512 + 255) / 256;

    prepA_kernel<<<(int)(((long)BT * D_IN + 255) / 256), 256>>>(x, Ab);        // 0
    {
        long tot = 2L * G3 * D_IN + (long)G3 * H;
        prepB_all<<<(int)((tot + 255) / 256), 256>>>(
            Wih1, Wih2, Wih2 + (size_t)D_IN * G3, B1, B2, B3);                 // 1
    }
    prepWhh<<<wgrid, 256>>>(Whh1, Wr1);                                        // 2 (+init)
    gemm_mma<<<ggrid, 256>>>(Ab, B1, 3 * D_IN, bih1, gi1, 0);                  // 3
    scan_tc<<<SNC, SNT, SCAN_SMEM>>>(gi1, Wr1, bhh1, tau1, out, 0, A3);        // 4
    prepWhh<<<wgrid, 256>>>(Whh2, Wr2);                                        // 5 (+re-init)
    gemm_mma<<<ggrid, 256>>>(Ab, B2, 3 * D_IN, bih2, gi2, 0);                  // 6
    gemm_mma<<<ggrid, 256>>>(A3, B3, 3 * H, nullptr, gi2, 1);                  // 7
    scan_tc<<<SNC, SNT, SCAN_SMEM>>>(gi2, Wr2, bhh2, tau2, out, 256, nullptr); // 8
}

// round 17
// speedup vs baseline: 1.0352x; 1.0352x over previous
#include <cuda_runtime.h>
#include <cuda_bf16.h>
#include <math.h>
#include <stdint.h>

#define D_IN 768
#define H    256
#define NB   64
#define NT   512
#define BT   (NB*NT)    // 32768
#define G3   768        // 3*H
#define SNC  64         // scan CTAs (each owns 4 h-columns)
#define SNT  256        // scan threads

// ---------------- scratch ----------------
__device__ float g_gi1[BT * (size_t)G3];                 // 96 MB time-major (t*64+b)
__device__ float g_gi2[BT * (size_t)G3];                 // 96 MB
__device__ __nv_bfloat16 g_Abuf[BT * (size_t)(3*D_IN)];  // [x_hi|x_lo|x_hi] time-major
__device__ __nv_bfloat16 g_A3[BT * (size_t)(3*H)];       // [h_hi|h_lo|h_hi] time-major
__device__ __nv_bfloat16 g_B1[(size_t)G3 * (3*D_IN)];
__device__ __nv_bfloat16 g_B2[(size_t)G3 * (3*D_IN)];
__device__ __nv_bfloat16 g_B3[(size_t)G3 * (3*H)];
__device__ __nv_bfloat16 g_hsplit[2][NB * 512];          // h state [b][hi(256)|lo(256)]
__device__ __nv_bfloat16 g_Wr1[SNC * 16 * 512];          // per-CTA scan weights [Whi|Wlo]
__device__ __nv_bfloat16 g_Wr2[SNC * 16 * 512];
__device__ unsigned g_cnt;                               // monotonic barrier counter

// ---------------- helpers ----------------
__device__ __forceinline__ uint32_t smem_u32(const void* p) {
    uint32_t a;
    asm("{ .reg .u64 t; cvta.to.shared.u64 t, %1; cvt.u32.u64 %0, t; }" : "=r"(a) : "l"(p));
    return a;
}
__device__ __forceinline__ void ldsm_x4(uint32_t& r0, uint32_t& r1, uint32_t& r2, uint32_t& r3,
                                        uint32_t addr) {
    asm volatile("ldmatrix.sync.aligned.m8n8.x4.shared.b16 {%0,%1,%2,%3}, [%4];"
                 : "=r"(r0), "=r"(r1), "=r"(r2), "=r"(r3) : "r"(addr));
}
__device__ __forceinline__ void mma_bf16(float* c, const uint32_t* a, const uint32_t* b) {
    asm volatile("mma.sync.aligned.m16n8k16.row.col.f32.bf16.bf16.f32 "
                 "{%0,%1,%2,%3}, {%4,%5,%6,%7}, {%8,%9}, {%0,%1,%2,%3};"
                 : "+f"(c[0]), "+f"(c[1]), "+f"(c[2]), "+f"(c[3])
                 : "r"(a[0]), "r"(a[1]), "r"(a[2]), "r"(a[3]), "r"(b[0]), "r"(b[1]));
}
__device__ __forceinline__ void cp16(uint32_t dst, const void* src) {
    asm volatile("cp.async.cg.shared.global [%0], [%1], 16;" :: "r"(dst), "l"(src));
}
__device__ __forceinline__ void cp_commit() { asm volatile("cp.async.commit_group;"); }
__device__ __forceinline__ void cp_wait1()  { asm volatile("cp.async.wait_group 1;"); }
__device__ __forceinline__ void cp_wait0()  { asm volatile("cp.async.wait_group 0;"); }

// gemm smem tile swizzle (64B rows, proven)
__device__ __forceinline__ uint32_t sw_off(int row, int c) {
    return ((uint32_t)row << 6) + (((uint32_t)(c ^ ((row >> 1) & 3))) << 4);
}
// scan smem tile swizzle (1024B rows, 16B chunks)
__device__ __forceinline__ uint32_t sw1k(int row, int c) {
    return ((uint32_t)row << 10) + (((uint32_t)(c ^ (row & 7))) << 4);
}
__device__ __forceinline__ float sigmoidf_(float x) {
    return 1.0f / (1.0f + __expf(-x));
}
__device__ __forceinline__ float tanhf_(float x) {
    float e = __expf(-2.0f * x);
    return (1.0f - e) / (1.0f + e);
}

// ---------------- prep kernels ----------------
__global__ void prepA_kernel(const float* __restrict__ x, __nv_bfloat16* __restrict__ A) {
    long i = (long)blockIdx.x * blockDim.x + threadIdx.x;
    if (i >= (long)BT * D_IN) return;
    int k = (int)(i % D_IN);
    long row = i / D_IN;              // b*512 + t
    int b = (int)(row >> 9), t = (int)(row & 511);
    float v = x[i];
    __nv_bfloat16 hi = __float2bfloat16(v);
    __nv_bfloat16 lo = __float2bfloat16(v - __bfloat162float(hi));
    long orow = ((long)t * 64 + b) * (3 * D_IN);
    A[orow + k] = hi;
    A[orow + D_IN + k] = lo;
    A[orow + 2 * D_IN + k] = hi;
}

__device__ __forceinline__ void prep_one(const float* __restrict__ W, int Kin,
                                         __nv_bfloat16* __restrict__ Bm, long idx) {
    int n = (int)(idx / Kin), k = (int)(idx % Kin);
    float v = W[(size_t)k * G3 + n];
    __nv_bfloat16 hi = __float2bfloat16(v);
    __nv_bfloat16 lo = __float2bfloat16(v - __bfloat162float(hi));
    size_t o = (size_t)n * (3 * Kin);
    Bm[o + k] = hi;
    Bm[o + Kin + k] = hi;
    Bm[o + 2 * Kin + k] = lo;
}

__global__ void prepB_all(const float* __restrict__ W1, const float* __restrict__ W2,
                          const float* __restrict__ W3,
                          __nv_bfloat16* __restrict__ B1, __nv_bfloat16* __restrict__ B2,
                          __nv_bfloat16* __restrict__ B3) {
    long i = (long)blockIdx.x * blockDim.x + threadIdx.x;
    const long n1 = (long)G3 * D_IN;
    const long n3 = (long)G3 * H;
    if (i < n1)               prep_one(W1, D_IN, B1, i);
    else if (i < 2 * n1)      prep_one(W2, D_IN, B2, i - n1);
    else if (i < 2 * n1 + n3) prep_one(W3, H,    B3, i - 2 * n1);
}

// per-CTA scan weights (16-row tiles, rows 12-15 zero) + zero h + reset barrier
__global__ void prepWhh(const float* __restrict__ Whh, __nv_bfloat16* __restrict__ dst) {
    long i = (long)blockIdx.x * blockDim.x + threadIdx.x;
    if (i < 2L * NB * 512) ((__nv_bfloat16*)g_hsplit)[i] = __float2bfloat16(0.0f);
    if (i == 0) g_cnt = 0u;
    if (i >= (long)SNC * 16 * 512) return;
    int cb = (int)(i / (16 * 512));
    int rem = (int)(i % (16 * 512));
    int nn = rem / 512, k2 = rem % 512;
    if (nn >= 12) { dst[i] = __float2bfloat16(0.0f); return; }
    int g = nn >> 2, j = nn & 3;
    int wcol = g * 256 + cb * 4 + j;
    float v = Whh[(size_t)(k2 & 255) * G3 + wcol];
    __nv_bfloat16 hi = __float2bfloat16(v);
    dst[i] = (k2 < 256) ? hi : __float2bfloat16(v - __bfloat162float(hi));
}

// ---------------- HMMA GEMM (proven inner loop; optional dual-B dispatch) ----------------
// If Bm2 != null, grid.x = 12: blocks 0..5 do (Bm,bias,C), blocks 6..11 do (Bm2,bias2,C2).
__global__ void __launch_bounds__(256)
gemm_mma(const __nv_bfloat16* __restrict__ A,
         const __nv_bfloat16* __restrict__ Bm,  const __nv_bfloat16* __restrict__ Bm2,
         int K,
         const float* __restrict__ bias, const float* __restrict__ bias2,
         float* __restrict__ C, float* __restrict__ C2, int acc)
{
    __shared__ __align__(1024) char smA[2][8192];
    __shared__ __align__(1024) char smB[2][8192];

    const int tid = threadIdx.x;
    const int wid = tid >> 5, lid = tid & 31;
    const int warp_m = wid & 3, warp_n = wid >> 2;
    const int m0 = blockIdx.y * 128;

    int nb = blockIdx.x;
    const __nv_bfloat16* Bsel = Bm;
    const float* bsel = bias;
    float* Csel = C;
    if (Bm2 && nb >= 6) { Bsel = Bm2; bsel = bias2; Csel = C2; nb -= 6; }
    const int n0 = nb * 128;

    const __nv_bfloat16* Ag = A + (size_t)m0 * K;
    const __nv_bfloat16* Bg = Bsel + (size_t)n0 * K;

    const uint32_t sA[2] = { smem_u32(smA[0]), smem_u32(smA[1]) };
    const uint32_t sB[2] = { smem_u32(smB[0]), smem_u32(smB[1]) };

    const int lrow0 = tid >> 2;
    const int lc    = tid & 3;
    const uint32_t loff0 = sw_off(lrow0, lc);
    const uint32_t loff1 = sw_off(lrow0 + 64, lc);

    float accf[2][8][4];
#pragma unroll
    for (int i = 0; i < 2; i++)
#pragma unroll
        for (int j = 0; j < 8; j++)
#pragma unroll
            for (int q = 0; q < 4; q++) accf[i][j][q] = 0.0f;

    const int nk = K >> 5;

    {
        const char* ga0 = (const char*)(Ag + (size_t)lrow0 * K + lc * 8);
        const char* ga1 = (const char*)(Ag + (size_t)(lrow0 + 64) * K + lc * 8);
        const char* gb0 = (const char*)(Bg + (size_t)lrow0 * K + lc * 8);
        const char* gb1 = (const char*)(Bg + (size_t)(lrow0 + 64) * K + lc * 8);
        cp16(sA[0] + loff0, ga0); cp16(sA[0] + loff1, ga1);
        cp16(sB[0] + loff0, gb0); cp16(sB[0] + loff1, gb1);
        cp_commit();
    }

    const int a_row = (lid & 15);
    const int a_cd  = (lid >> 4);
    const int b_row = (lid & 7) + ((lid >> 4) & 1) * 8;
    const int b_cd  = (lid >> 3) & 1;

    for (int kc = 0; kc < nk; kc++) {
        if (kc + 1 < nk) {
            int koff = (kc + 1) * 32;
            int st = (kc + 1) & 1;
            const char* ga0 = (const char*)(Ag + (size_t)lrow0 * K + koff + lc * 8);
            const char* ga1 = (const char*)(Ag + (size_t)(lrow0 + 64) * K + koff + lc * 8);
            const char* gb0 = (const char*)(Bg + (size_t)lrow0 * K + koff + lc * 8);
            const char* gb1 = (const char*)(Bg + (size_t)(lrow0 + 64) * K + koff + lc * 8);
            cp16(sA[st] + loff0, ga0); cp16(sA[st] + loff1, ga1);
            cp16(sB[st] + loff0, gb0); cp16(sB[st] + loff1, gb1);
        }
        cp_commit();
        cp_wait1();
        __syncthreads();

        const uint32_t aT = sA[kc & 1], bT = sB[kc & 1];
#pragma unroll
        for (int ks = 0; ks < 2; ks++) {
            uint32_t afr[2][4];
#pragma unroll
            for (int fm = 0; fm < 2; fm++) {
                int row = warp_m * 32 + fm * 16 + a_row;
                ldsm_x4(afr[fm][0], afr[fm][1], afr[fm][2], afr[fm][3],
                        aT + sw_off(row, 2 * ks + a_cd));
            }
            uint32_t bfr[8][2];
#pragma unroll
            for (int ng = 0; ng < 4; ng++) {
                int row = warp_n * 64 + ng * 16 + b_row;
                uint32_t r0, r1, r2, r3;
                ldsm_x4(r0, r1, r2, r3, bT + sw_off(row, 2 * ks + b_cd));
                bfr[ng * 2][0] = r0;     bfr[ng * 2][1] = r1;
                bfr[ng * 2 + 1][0] = r2; bfr[ng * 2 + 1][1] = r3;
            }
#pragma unroll
            for (int fm = 0; fm < 2; fm++)
#pragma unroll
                for (int fn = 0; fn < 8; fn++)
                    mma_bf16(accf[fm][fn], afr[fm], bfr[fn]);
        }
        __syncthreads();
    }

#pragma unroll
    for (int fm = 0; fm < 2; fm++) {
        int row = m0 + warp_m * 32 + fm * 16 + (lid >> 2);
#pragma unroll
        for (int fn = 0; fn < 8; fn++) {
            int colg = n0 + warp_n * 64 + fn * 8 + (lid & 3) * 2;
            float2 v0 = make_float2(accf[fm][fn][0], accf[fm][fn][1]);
            float2 v1 = make_float2(accf[fm][fn][2], accf[fm][fn][3]);
            if (bsel) {
                float b0 = bsel[colg], b1 = bsel[colg + 1];
                v0.x += b0; v0.y += b1; v1.x += b0; v1.y += b1;
            }
            float* p0 = Csel + (size_t)row * G3 + colg;
            float* p1 = Csel + (size_t)(row + 8) * G3 + colg;
            if (acc) {
                float2 o0 = *(const float2*)p0;
                float2 o1 = *(const float2*)p1;
                v0.x += o0.x; v0.y += o0.y; v1.x += o1.x; v1.y += o1.y;
            }
            *(float2*)p0 = v0;
            *(float2*)p1 = v1;
        }
    }
}

// ---------------- tensor-core persistent scan (v5: split accumulator chains) ----------------
#define AS_OFF   0
#define BS_OFF   65536
#define PART_OFF 81920
#define PSTR     20
#define SCAN_SMEM (PART_OFF + 2*64*PSTR*4)

__global__ void __launch_bounds__(SNT, 1)
scan_tc(const float* __restrict__ gi, const __nv_bfloat16* __restrict__ Wsc,
        const float* __restrict__ bhh, const float* __restrict__ tau,
        float* __restrict__ out, int outc0, __nv_bfloat16* __restrict__ a3)
{
    extern __shared__ char sm[];
    const uint32_t as_u = smem_u32(sm + AS_OFF);
    const uint32_t bs_u = smem_u32(sm + BS_OFF);
    float* part = (float*)(sm + PART_OFF);

    const int cb  = blockIdx.x;
    const int tid = threadIdx.x;
    const int wid = tid >> 5, lid = tid & 31;
    const int c0  = cb * 4;
    const int wm  = wid & 3;          // M-tile (16 rows)
    const int khh = wid >> 2;         // k-half

    const int eb  = tid >> 2;         // epilogue batch row (0..63)
    const int ejj = tid & 3;          // epilogue col (0..3)
    const int col = c0 + ejj;

    float bias[3];
#pragma unroll
    for (int g = 0; g < 3; g++) bias[g] = bhh[g * 256 + col];
    const float invt = 1.0f / tau[0];
    float hold1 = 0.0f;               // exact fp32 recurrent carry

    // stationary weights -> smem (one-time): 16 rows x 64 chunks
    for (int i = tid; i < 1024; i += SNT) {
        int n = i >> 6, c = i & 63;
        cp16(bs_u + sw1k(n, c), Wsc + (size_t)cb * 16 * 512 + n * 512 + c * 8);
    }
    cp_commit();
    cp_wait0();
    __syncthreads();

    // resident B fragments: per kt one x4 (16 B-rows = 2 n8-tiles), hi + lo
    const int b_row = (lid & 7) + ((lid >> 4) & 1) * 8;
    const int b_cd  = (lid >> 3) & 1;
    uint32_t bH[8][4], bL[8][4];
#pragma unroll
    for (int ii = 0; ii < 8; ii++) {
        int kt = khh * 8 + ii;
        ldsm_x4(bH[ii][0], bH[ii][1], bH[ii][2], bH[ii][3],
                bs_u + sw1k(b_row, 2 * kt + b_cd));
        ldsm_x4(bL[ii][0], bL[ii][1], bL[ii][2], bL[ii][3],
                bs_u + sw1k(b_row, 2 * (16 + kt) + b_cd));
    }

    // gi register prefetch for t=0 (one col per thread)
    const float* g0 = gi + (size_t)eb * G3 + col;
    float pr = g0[0], pz = g0[256], pn = g0[512];

    const int a_row = wm * 16 + (lid & 15);
    const int a_cd  = lid >> 4;
    const int fl_c  = (lid < 16) ? (khh * 16 + lid) : (32 + khh * 16 + (lid - 16));
    const bool own0 = ((lid >> 3) & 1) == 0;

    for (int t = 0; t < NT; t++) {
        const int cur = t & 1, nxt = cur ^ 1;
        const __nv_bfloat16* hsrc = g_hsplit[cur];

        // prefetch gi for t+1 (independent; hides behind MMA)
        int tnn = (t + 1 < NT) ? t + 1 : t;
        const float* gx = gi + ((size_t)tnn * 64 + eb) * G3 + col;
        float tr = gx[0], tz = gx[256], tn2 = gx[512];

        // A fill, two groups by k-half
        if (own0) {
#pragma unroll
            for (int i = 0; i < 16; i++) {
                int row = wm * 16 + i;
                cp16(as_u + sw1k(row, fl_c), hsrc + row * 512 + fl_c * 8);
            }
        }
        cp_commit();
        if (!own0) {
#pragma unroll
            for (int i = 0; i < 16; i++) {
                int row = wm * 16 + i;
                cp16(as_u + sw1k(row, fl_c), hsrc + row * 512 + fl_c * 8);
            }
        }
        cp_commit();

        // 6 independent accumulator chains (3 product types x 2 n-tiles), depth 8
        float cH0[4], cH1[4], cL0[4], cL1[4], cW0[4], cW1[4];
#pragma unroll
        for (int q = 0; q < 4; q++) {
            cH0[q] = 0.0f; cH1[q] = 0.0f; cL0[q] = 0.0f;
            cL1[q] = 0.0f; cW0[q] = 0.0f; cW1[q] = 0.0f;
        }

#pragma unroll
        for (int half = 0; half < 2; half++) {
            if (half == 0) cp_wait1(); else cp_wait0();
            __syncwarp();
#pragma unroll
            for (int jj2 = 0; jj2 < 4; jj2++) {
                int ii = half * 4 + jj2;
                int kt = khh * 8 + ii;
                uint32_t aH[4], aL[4];
                ldsm_x4(aH[0], aH[1], aH[2], aH[3], as_u + sw1k(a_row, 2 * kt + a_cd));
                ldsm_x4(aL[0], aL[1], aL[2], aL[3], as_u + sw1k(a_row, 2 * (16 + kt) + a_cd));
                mma_bf16(cH0, aH, &bH[ii][0]);
                mma_bf16(cH1, aH, &bH[ii][2]);
                mma_bf16(cL0, aL, &bH[ii][0]);
                mma_bf16(cL1, aL, &bH[ii][2]);
                mma_bf16(cW0, aH, &bL[ii][0]);
                mma_bf16(cW1, aH, &bL[ii][2]);
            }
        }

        // exchange partials: part[(khh*64 + row)*PSTR + n]
        {
            int r0 = wm * 16 + (lid >> 2);
            int cc = (lid & 3) * 2;
            float2 v00 = make_float2(cH0[0] + cL0[0] + cW0[0], cH0[1] + cL0[1] + cW0[1]);
            float2 v01 = make_float2(cH0[2] + cL0[2] + cW0[2], cH0[3] + cL0[3] + cW0[3]);
            float2 v10 = make_float2(cH1[0] + cL1[0] + cW1[0], cH1[1] + cL1[1] + cW1[1]);
            float2 v11 = make_float2(cH1[2] + cL1[2] + cW1[2], cH1[3] + cL1[3] + cW1[3]);
            *(float2*)&part[(khh * 64 + r0) * PSTR + cc]         = v00;
            *(float2*)&part[(khh * 64 + r0 + 8) * PSTR + cc]     = v01;
            *(float2*)&part[(khh * 64 + r0) * PSTR + 8 + cc]     = v10;
            *(float2*)&part[(khh * 64 + r0 + 8) * PSTR + 8 + cc] = v11;
        }
        __syncthreads();

        // gates (one col per thread; register carry + register gi)
        float hnew;
        {
            const float* p0 = part + eb * PSTR;
            const float* p1 = part + (64 + eb) * PSTR;
            float sr = p0[ejj]     + p1[ejj];
            float sz = p0[4 + ejj] + p1[4 + ejj];
            float sn = p0[8 + ejj] + p1[8 + ejj];
            float r = sigmoidf_(pr + sr + bias[0]);
            float z = sigmoidf_(pz + sz + bias[1]);
            float n = tanhf_(pn + r * (sn + bias[2]));
            float hc = (1.0f - z) * n + z * hold1;
            hnew = hold1 + invt * (hc - hold1);
            hold1 = hnew;

            // barrier-critical stores only: h state
            __nv_bfloat16 nh = __float2bfloat16(hnew);
            __nv_bfloat16 nl = __float2bfloat16(hnew - __bfloat162float(nh));
            __nv_bfloat16* hd = g_hsplit[nxt] + eb * 512 + col;
            hd[0]   = nh;
            hd[256] = nl;
        }
        __syncthreads();   // h stores sequenced before tid0's release-arrival

        if (tid == 0) {
            asm volatile("red.release.gpu.global.add.u32 [%0], %1;"
                         :: "l"(&g_cnt), "r"(1u) : "memory");
        }

        // non-critical stores hidden under the barrier wait
        out[((size_t)eb * NT + t) * 512 + outc0 + col] = hnew;
        if (a3) {
            __nv_bfloat16 nh = __float2bfloat16(hnew);
            __nv_bfloat16 nl = __float2bfloat16(hnew - __bfloat162float(nh));
            __nv_bfloat16* ad = a3 + ((size_t)t * 64 + eb) * (3 * H) + col;
            ad[0]   = nh;
            ad[256] = nl;
            ad[512] = nh;
        }

        if (tid == 0) {
            unsigned tgt = (unsigned)SNC * (unsigned)(t + 1);
            unsigned v;
            do {
                asm volatile("ld.acquire.gpu.global.u32 %0, [%1];"
                             : "=r"(v) : "l"(&g_cnt) : "memory");
            } while (v < tgt);
        }
        __syncthreads();

        pr = tr; pz = tz; pn = tn2;
    }
}

// ---------------- launch (single stream; capture-safe) ----------------
extern "C" void kernel_launch(void* const* d_in, const int* in_sizes, int n_in,
                              void* d_out, int out_size) {
    const float* x    = (const float*)d_in[0];
    const float* tau1 = (const float*)d_in[1];
    const float* tau2 = (const float*)d_in[2];
    const float* Wih1 = (const float*)d_in[3];
    const float* Whh1 = (const float*)d_in[4];
    const float* bih1 = (const float*)d_in[5];
    const float* bhh1 = (const float*)d_in[6];
    const float* Wih2 = (const float*)d_in[7];
    const float* Whh2 = (const float*)d_in[8];
    const float* bih2 = (const float*)d_in[9];
    const float* bhh2 = (const float*)d_in[10];
    float* out = (float*)d_out;

    float *gi1, *gi2;
    __nv_bfloat16 *Ab, *A3, *B1, *B2, *B3, *Wr1, *Wr2;
    cudaGetSymbolAddress((void**)&gi1, g_gi1);
    cudaGetSymbolAddress((void**)&gi2, g_gi2);
    cudaGetSymbolAddress((void**)&Ab,  g_Abuf);
    cudaGetSymbolAddress((void**)&A3,  g_A3);
    cudaGetSymbolAddress((void**)&B1,  g_B1);
    cudaGetSymbolAddress((void**)&B2,  g_B2);
    cudaGetSymbolAddress((void**)&B3,  g_B3);
    cudaGetSymbolAddress((void**)&Wr1, g_Wr1);
    cudaGetSymbolAddress((void**)&Wr2, g_Wr2);

    cudaFuncSetAttribute(scan_tc,
                         cudaFuncAttributeMaxDynamicSharedMemorySize, SCAN_SMEM);

    dim3 gdual(12, BT / 128);         // fused gemm1+gemm2
    dim3 gsing(6, BT / 128);
    int wgrid = (SNC * 16 * 512 + 255) / 256;

    prepA_kernel<<<(int)(((long)BT * D_IN + 255) / 256), 256>>>(x, Ab);        // 0
    {
        long tot = 2L * G3 * D_IN + (long)G3 * H;
        prepB_all<<<(int)((tot + 255) / 256), 256>>>(
            Wih1, Wih2, Wih2 + (size_t)D_IN * G3, B1, B2, B3);                 // 1
    }
    prepWhh<<<wgrid, 256>>>(Whh1, Wr1);                                        // 2 (+init)
    // fused: gi1 = x@W_ih1 + b_ih1 ; gi2 = x@W_ih2[:768] + b_ih2
    gemm_mma<<<gdual, 256>>>(Ab, B1, B2, 3 * D_IN, bih1, bih2, gi1, gi2, 0);   // 3
    scan_tc<<<SNC, SNT, SCAN_SMEM>>>(gi1, Wr1, bhh1, tau1, out, 0, A3);        // 4
    prepWhh<<<wgrid, 256>>>(Whh2, Wr2);                                        // 5 (+re-init)
    // gi2 += h1 @ W_ih2[768:1024]
    gemm_mma<<<gsing, 256>>>(A3, B3, nullptr, 3 * H, nullptr, nullptr, gi2, nullptr, 1); // 6
    scan_tc<<<SNC, SNT, SCAN_SMEM>>>(gi2, Wr2, bhh2, tau2, out, 256, nullptr); // 7
}